// round 12
// baseline (speedup 1.0000x reference)
#include <cuda_runtime.h>
#include <cuda_bf16.h>
#include <cstdint>

#define NN 100000
#define EE 1600000
#define DD 128

// Scratch (allocation-free rule: __device__ globals)
__device__ float g_h   [NN * DD];
__device__ float g_h2  [NN * DD];
__device__ float g_agg [NN * DD];
__device__ int   g_src [EE];
__device__ int   g_dst [EE];
__device__ int   g_esrc[EE];
__device__ int   g_degi[NN];
__device__ int   g_rowptr[NN + 1];
__device__ int   g_cursor[NN];
__device__ int   g_bsum[128];
__device__ int   g_boff[128];
__device__ int   g_is64;

// ===========================================================================
// PTX helpers (sm_80-compatible only: ldmatrix + mma.sync; NO tcgen05 — the
// harness compiles PTX at target compute_103, which rejects 'a' features)
// ===========================================================================
__device__ __forceinline__ uint32_t smem_u32(const void* p) {
    uint32_t a;
    asm("{ .reg .u64 t; cvta.to.shared.u64 t, %1; cvt.u32.u64 %0, t; }"
        : "=r"(a) : "l"(p));
    return a;
}
__device__ __forceinline__ void ldsm_x4(uint32_t* r, uint32_t addr) {
    asm volatile("ldmatrix.sync.aligned.m8n8.x4.shared.b16 {%0,%1,%2,%3}, [%4];"
                 : "=r"(r[0]), "=r"(r[1]), "=r"(r[2]), "=r"(r[3]) : "r"(addr));
}
__device__ __forceinline__ void mma16816(float* d, const uint32_t* a,
                                         const uint32_t* b) {
    asm volatile(
        "mma.sync.aligned.m16n8k16.row.col.f32.bf16.bf16.f32 "
        "{%0,%1,%2,%3}, {%4,%5,%6,%7}, {%8,%9}, {%0,%1,%2,%3};"
        : "+f"(d[0]), "+f"(d[1]), "+f"(d[2]), "+f"(d[3])
        : "r"(a[0]), "r"(a[1]), "r"(a[2]), "r"(a[3]), "r"(b[0]), "r"(b[1]));
}

// ===========================================================================
// Smem tile layout: bf16 [128][BSTRIDE], BSTRIDE=136.
// lin:  A_hi, A_lo, B_hi, B_lo           (4 regions, 139264 B)
// sage: A_hi, A_lo, BL_hi, BL_lo, BR_hi, BR_lo (6 regions, 208896 B)
// ===========================================================================
#define BSTRIDE 136
#define W_ELEMS (128 * BSTRIDE)       // 17408 bf16 per hi or lo region
#define TILE_B  (W_ELEMS * 2)         // 34816 bytes
#define R_A_HI  0
#define R_A_LO  (TILE_B)
#define R_B_HI  (2 * TILE_B)
#define LIN_SMEM  (4 * TILE_B)        // 139264
#define SAGE_SMEM (6 * TILE_B)        // 208896
#define GEMM_T   256                  // 8 warps, warp grid 4x2, tile 32x64

// Pre-converted weights: [6 weights][hi 17408 | lo 17408] bf16, smem layout.
__device__ __align__(16) __nv_bfloat16 g_wbf[6 * 2 * W_ELEMS];

// split fp32 pair -> bf16 hi/lo into A regions
__device__ __forceinline__ void cvt_store_pair(char* sm, int r, int c, float2 v) {
    __nv_bfloat16 h0 = __float2bfloat16(v.x);
    __nv_bfloat16 h1 = __float2bfloat16(v.y);
    __nv_bfloat16 l0 = __float2bfloat16(v.x - __bfloat162float(h0));
    __nv_bfloat16 l1 = __float2bfloat16(v.y - __bfloat162float(h1));
    uint32_t off = (uint32_t)(r * BSTRIDE + c) * 2;
    *reinterpret_cast<__nv_bfloat162*>(sm + R_A_HI + off) = __halves2bfloat162(h0, h1);
    *reinterpret_cast<__nv_bfloat162*>(sm + R_A_LO + off) = __halves2bfloat162(l0, l1);
}

// Weight prep: 16 blocks per weight, 256 threads, 4 elems/thread.
__global__ void prep_weights_kernel(const float* __restrict__ w0,
                                    const float* __restrict__ w1,
                                    const float* __restrict__ w2,
                                    const float* __restrict__ w3,
                                    const float* __restrict__ w4,
                                    const float* __restrict__ w5) {
    const float* ws[6] = {w0, w1, w2, w3, w4, w5};
    int w = blockIdx.x >> 4;
    int eb = ((blockIdx.x & 15) << 10) + (threadIdx.x << 2);   // elem base, mult of 4
    float4 v = *reinterpret_cast<const float4*>(ws[w] + eb);
    int r = eb >> 7, c = eb & 127;
    __nv_bfloat16 h0 = __float2bfloat16(v.x);
    __nv_bfloat16 h1 = __float2bfloat16(v.y);
    __nv_bfloat16 h2 = __float2bfloat16(v.z);
    __nv_bfloat16 h3 = __float2bfloat16(v.w);
    __nv_bfloat16 l0 = __float2bfloat16(v.x - __bfloat162float(h0));
    __nv_bfloat16 l1 = __float2bfloat16(v.y - __bfloat162float(h1));
    __nv_bfloat16 l2 = __float2bfloat16(v.z - __bfloat162float(h2));
    __nv_bfloat16 l3 = __float2bfloat16(v.w - __bfloat162float(h3));
    __nv_bfloat16* hi = g_wbf + (size_t)w * 2 * W_ELEMS;
    __nv_bfloat16* lo = hi + W_ELEMS;
    int o = r * BSTRIDE + c;
    *reinterpret_cast<__nv_bfloat162*>(hi + o)     = __halves2bfloat162(h0, h1);
    *reinterpret_cast<__nv_bfloat162*>(hi + o + 2) = __halves2bfloat162(h2, h3);
    *reinterpret_cast<__nv_bfloat162*>(lo + o)     = __halves2bfloat162(l0, l1);
    *reinterpret_cast<__nv_bfloat162*>(lo + o + 2) = __halves2bfloat162(l2, l3);
}

// Copy one pre-converted weight (hi+lo, contiguous 69632 B) into smem.
__device__ __forceinline__ void copy_weight(char* sm, uint32_t dstOff, int widx,
                                            int tid) {
    const uint4* src = reinterpret_cast<const uint4*>(g_wbf + (size_t)widx * 2 * W_ELEMS);
    uint4* dst = reinterpret_cast<uint4*>(sm + dstOff);
    #pragma unroll
    for (int i = 0; i < 17; i++) {
        int idx = tid + i * GEMM_T;
        dst[idx] = src[idx];
    }
}

// Mainloop: warp tile 32x64 (wr 0..3, wc 0..1), 3-term split, accumulate.
// bHi = smem offset of weight hi region; lo is contiguous at bHi + TILE_B.
__device__ __forceinline__ void mma_tile(uint32_t sb, float acc[2][8][4],
                                         int wr, int wc, int l, uint32_t bHi) {
    uint32_t bLo = bHi + TILE_B;
    #pragma unroll 2
    for (int k = 0; k < 8; k++) {
        uint32_t ah0[4], ah1[4], al0[4], al1[4];
        uint32_t arow0 = (uint32_t)(wr * 32 + (l & 15));
        uint32_t acolk = (uint32_t)(k * 16 + (l >> 4) * 8);
        uint32_t aoff0 = (arow0 * BSTRIDE + acolk) * 2;
        uint32_t aoff1 = ((arow0 + 16) * BSTRIDE + acolk) * 2;
        ldsm_x4(ah0, sb + R_A_HI + aoff0);
        ldsm_x4(ah1, sb + R_A_HI + aoff1);
        ldsm_x4(al0, sb + R_A_LO + aoff0);
        ldsm_x4(al1, sb + R_A_LO + aoff1);
        #pragma unroll
        for (int nfp = 0; nfp < 4; nfp++) {
            uint32_t bh4[4], bl4[4];
            uint32_t brow = (uint32_t)(wc * 64 + nfp * 16 + ((l >> 4) & 1) * 8 + (l & 7));
            uint32_t bcol = (uint32_t)(k * 16 + ((l >> 3) & 1) * 8);
            uint32_t boff = (brow * BSTRIDE + bcol) * 2;
            ldsm_x4(bh4, sb + bHi + boff);
            ldsm_x4(bl4, sb + bLo + boff);
            int nf0 = nfp * 2, nf1 = nfp * 2 + 1;
            mma16816(acc[0][nf0], ah0, bh4 + 0);
            mma16816(acc[1][nf0], ah1, bh4 + 0);
            mma16816(acc[0][nf1], ah0, bh4 + 2);
            mma16816(acc[1][nf1], ah1, bh4 + 2);
            mma16816(acc[0][nf0], ah0, bl4 + 0);
            mma16816(acc[1][nf0], ah1, bl4 + 0);
            mma16816(acc[0][nf1], ah0, bl4 + 2);
            mma16816(acc[1][nf1], ah1, bl4 + 2);
            mma16816(acc[0][nf0], al0, bh4 + 0);
            mma16816(acc[1][nf0], al1, bh4 + 0);
            mma16816(acc[0][nf1], al0, bh4 + 2);
            mma16816(acc[1][nf1], al1, bh4 + 2);
        }
    }
}

__device__ __forceinline__ void epilogue(float acc[2][8][4], const float* bias,
                                         float* Y, int rowBase, int wr, int wc,
                                         int l) {
    #pragma unroll
    for (int mf = 0; mf < 2; mf++) {
        #pragma unroll
        for (int nf = 0; nf < 8; nf++) {
            int col = wc * 64 + nf * 8 + (l & 3) * 2;
            float b0 = __ldg(bias + col), b1 = __ldg(bias + col + 1);
            int row0 = rowBase + wr * 32 + mf * 16 + (l >> 2);
            if (row0 < NN) {
                float2 v;
                v.x = fmaxf(acc[mf][nf][0] + b0, 0.f);
                v.y = fmaxf(acc[mf][nf][1] + b1, 0.f);
                *reinterpret_cast<float2*>(Y + (size_t)row0 * DD + col) = v;
            }
            int row1 = row0 + 8;
            if (row1 < NN) {
                float2 v;
                v.x = fmaxf(acc[mf][nf][2] + b0, 0.f);
                v.y = fmaxf(acc[mf][nf][3] + b1, 0.f);
                *reinterpret_cast<float2*>(Y + (size_t)row1 * DD + col) = v;
            }
        }
    }
}

// ===========================================================================
// Edge preprocessing: dtype detect, int32 edge lists, CSR build
// ===========================================================================
__global__ void detect_kernel(const long long* __restrict__ ei) {
    int t = threadIdx.x;
    long long v = ei[(size_t)(t & 15) * (EE / 16) + 3];
    unsigned bad = __ballot_sync(0xFFFFFFFF, v < 0 || v >= NN);
    if (t == 0) g_is64 = (bad == 0) ? 1 : 0;
}

__global__ void zero_degi_kernel() {
    int i = blockIdx.x * blockDim.x + threadIdx.x;
    if (i < NN) g_degi[i] = 0;
}

__global__ void convert_kernel(const void* __restrict__ ei_raw) {
    int e = blockIdx.x * blockDim.x + threadIdx.x;
    if (e >= EE) return;
    int s, d;
    if (g_is64) {
        const long long* ei = (const long long*)ei_raw;
        s = (int)ei[e];
        d = (int)ei[EE + e];
    } else {
        const int* ei = (const int*)ei_raw;
        s = ei[e];
        d = ei[EE + e];
    }
    g_src[e] = s;
    g_dst[e] = d;
    atomicAdd(&g_degi[d], 1);
}

// --- 3-phase parallel exclusive scan over g_degi -> g_rowptr / g_cursor ---
#define SCAN_BT 1024
#define SCAN_NB ((NN + SCAN_BT - 1) / SCAN_BT)   // 98

__global__ void scan_block_kernel() {
    __shared__ int ss[SCAN_BT];
    int t = threadIdx.x;
    int i = blockIdx.x * SCAN_BT + t;
    int v = (i < NN) ? g_degi[i] : 0;
    ss[t] = v;
    __syncthreads();
    for (int d = 1; d < SCAN_BT; d <<= 1) {
        int u = (t >= d) ? ss[t - d] : 0;
        __syncthreads();
        ss[t] += u;
        __syncthreads();
    }
    if (i < NN) g_rowptr[i] = ss[t] - v;   // exclusive within block
    if (t == SCAN_BT - 1) g_bsum[blockIdx.x] = ss[t];
}

__global__ void scan_bsum_kernel() {
    __shared__ int ss[128];
    int t = threadIdx.x;
    int v = (t < SCAN_NB) ? g_bsum[t] : 0;
    ss[t] = v;
    __syncthreads();
    for (int d = 1; d < 128; d <<= 1) {
        int u = (t >= d) ? ss[t - d] : 0;
        __syncthreads();
        ss[t] += u;
        __syncthreads();
    }
    g_boff[t] = ss[t] - v;   // exclusive
}

__global__ void scan_apply_kernel() {
    int i = blockIdx.x * SCAN_BT + threadIdx.x;
    if (i < NN) {
        int val = g_rowptr[i] + g_boff[blockIdx.x];
        g_rowptr[i] = val;
        g_cursor[i] = val;
    }
    if (i == 0) g_rowptr[NN] = EE;
}

__global__ void bucket_kernel() {
    int e = blockIdx.x * blockDim.x + threadIdx.x;
    if (e >= EE) return;
    int pos = atomicAdd(&g_cursor[g_dst[e]], 1);
    g_esrc[pos] = g_src[e];
}

// ===========================================================================
// Mean aggregation: warp per dst node, gather over CSR, write mean.
// ===========================================================================
__global__ void gather_mean_kernel(const float* __restrict__ H) {
    int w = (blockIdx.x * blockDim.x + threadIdx.x) >> 5;
    int lane = threadIdx.x & 31;
    if (w >= NN) return;
    int beg = g_rowptr[w], end = g_rowptr[w + 1];
    float4 acc = make_float4(0.f, 0.f, 0.f, 0.f);
    for (int base = beg; base < end; base += 32) {
        int cnt = min(32, end - base);
        int s = (lane < cnt) ? g_esrc[base + lane] : 0;
        for (int j = 0; j < cnt; j++) {
            int sj = __shfl_sync(0xFFFFFFFF, s, j);
            float4 v = reinterpret_cast<const float4*>(H + (size_t)sj * DD)[lane];
            acc.x += v.x; acc.y += v.y; acc.z += v.z; acc.w += v.w;
        }
    }
    float inv = (end > beg) ? 1.0f / (float)(end - beg) : 0.0f;
    acc.x *= inv; acc.y *= inv; acc.z *= inv; acc.w *= inv;
    reinterpret_cast<float4*>(g_agg + (size_t)w * DD)[lane] = acc;
}

// ===========================================================================
// GEMM 1: Y = relu(X @ W^T + b), weight pre-converted (index widx)
// ===========================================================================
__global__ __launch_bounds__(GEMM_T, 1)
void gemm_lin_kernel(const float* __restrict__ X, int widx,
                     const float* __restrict__ b, float* __restrict__ Y) {
    extern __shared__ char sm[];
    uint32_t sb = smem_u32(sm);
    int tid = threadIdx.x, wid = tid >> 5, l = tid & 31;
    int wr = wid >> 1, wc = wid & 1;
    int rowBase = blockIdx.x * 128;

    copy_weight(sm, R_B_HI, widx, tid);
    for (int idx = tid; idx < 128 * 64; idx += GEMM_T) {
        int r = idx >> 6, c = (idx & 63) * 2;
        int row = rowBase + r;
        float2 vx = make_float2(0.f, 0.f);
        if (row < NN) vx = *reinterpret_cast<const float2*>(X + (size_t)row * DD + c);
        cvt_store_pair(sm, r, c, vx);
    }
    __syncthreads();

    float acc[2][8][4];
    #pragma unroll
    for (int i = 0; i < 2; i++)
        #pragma unroll
        for (int j = 0; j < 8; j++)
            #pragma unroll
            for (int q = 0; q < 4; q++) acc[i][j][q] = 0.f;

    mma_tile(sb, acc, wr, wc, l, R_B_HI);
    epilogue(acc, b, Y, rowBase, wr, wc, l);
}

// ===========================================================================
// GEMM 2: Y = relu( mean @ Wl^T + bl + H @ Wr^T ), two phases, reg accum.
// Both weights resident in smem from the prologue.
// ===========================================================================
__global__ __launch_bounds__(GEMM_T, 1)
void gemm_sage_kernel(const float* __restrict__ H, int wl_idx,
                      const float* __restrict__ bl, int wr_idx,
                      float* __restrict__ Y) {
    extern __shared__ char sm[];
    uint32_t sb = smem_u32(sm);
    int tid = threadIdx.x, wid = tid >> 5, l = tid & 31;
    int wr = wid >> 1, wc = wid & 1;
    int rowBase = blockIdx.x * 128;

    copy_weight(sm, 2 * TILE_B, wl_idx, tid);
    copy_weight(sm, 4 * TILE_B, wr_idx, tid);
    // phase 1 A: mean
    for (int idx = tid; idx < 128 * 64; idx += GEMM_T) {
        int r = idx >> 6, c = (idx & 63) * 2;
        int row = rowBase + r;
        float2 va = make_float2(0.f, 0.f);
        if (row < NN) va = *reinterpret_cast<const float2*>(g_agg + (size_t)row * DD + c);
        cvt_store_pair(sm, r, c, va);
    }
    __syncthreads();

    float acc[2][8][4];
    #pragma unroll
    for (int i = 0; i < 2; i++)
        #pragma unroll
        for (int j = 0; j < 8; j++)
            #pragma unroll
            for (int q = 0; q < 4; q++) acc[i][j][q] = 0.f;

    mma_tile(sb, acc, wr, wc, l, 2 * TILE_B);
    __syncthreads();

    // phase 2 A: H
    for (int idx = tid; idx < 128 * 64; idx += GEMM_T) {
        int r = idx >> 6, c = (idx & 63) * 2;
        int row = rowBase + r;
        float2 va = make_float2(0.f, 0.f);
        if (row < NN) va = *reinterpret_cast<const float2*>(H + (size_t)row * DD + c);
        cvt_store_pair(sm, r, c, va);
    }
    __syncthreads();

    mma_tile(sb, acc, wr, wc, l, 4 * TILE_B);
    epilogue(acc, bl, Y, rowBase, wr, wc, l);
}

// ===========================================================================
extern "C" void kernel_launch(void* const* d_in, const int* in_sizes, int n_in,
                              void* d_out, int out_size) {
    const float* x     = (const float*)d_in[0];
    const void*  ei    = d_in[1];
    const float* W1    = (const float*)d_in[2];
    const float* b1    = (const float*)d_in[3];
    const float* W2    = (const float*)d_in[4];
    const float* b2    = (const float*)d_in[5];
    const float* c1_Wl = (const float*)d_in[6];
    const float* c1_bl = (const float*)d_in[7];
    const float* c1_Wr = (const float*)d_in[8];
    const float* c2_Wl = (const float*)d_in[9];
    const float* c2_bl = (const float*)d_in[10];
    const float* c2_Wr = (const float*)d_in[11];
    float* out = (float*)d_out;

    cudaFuncSetAttribute(gemm_lin_kernel,
                         cudaFuncAttributeMaxDynamicSharedMemorySize, LIN_SMEM);
    cudaFuncSetAttribute(gemm_sage_kernel,
                         cudaFuncAttributeMaxDynamicSharedMemorySize, SAGE_SMEM);

    float *p_h, *p_h2;
    cudaGetSymbolAddress((void**)&p_h, g_h);
    cudaGetSymbolAddress((void**)&p_h2, g_h2);

    int nb = (NN + 127) / 128;                      // 782 tiles
    int conv_blocks = (EE + 255) / 256;
    int gather_blocks = (NN * 32 + 255) / 256;      // one warp per node

    // weight pre-conversion (indices: 0=W1, 1=W2, 2=c1Wl, 3=c1Wr, 4=c2Wl, 5=c2Wr)
    prep_weights_kernel<<<96, 256>>>(W1, W2, c1_Wl, c1_Wr, c2_Wl, c2_Wr);

    // edge preprocessing + CSR build
    detect_kernel<<<1, 32>>>((const long long*)ei);
    zero_degi_kernel<<<(NN + 255) / 256, 256>>>();
    convert_kernel<<<conv_blocks, 256>>>(ei);
    scan_block_kernel<<<SCAN_NB, SCAN_BT>>>();
    scan_bsum_kernel<<<1, 128>>>();
    scan_apply_kernel<<<SCAN_NB, SCAN_BT>>>();
    bucket_kernel<<<conv_blocks, 256>>>();

    // layer 1
    gemm_lin_kernel<<<nb, GEMM_T, LIN_SMEM>>>(x, 0, b1, p_h);
    // sage 1
    gather_mean_kernel<<<gather_blocks, 256>>>(p_h);
    gemm_sage_kernel<<<nb, GEMM_T, SAGE_SMEM>>>(p_h, 2, c1_bl, 3, p_h2);
    // layer 2
    gemm_lin_kernel<<<nb, GEMM_T, LIN_SMEM>>>(p_h2, 1, b2, p_h);
    // sage 2 -> out
    gather_mean_kernel<<<gather_blocks, 256>>>(p_h);
    gemm_sage_kernel<<<nb, GEMM_T, SAGE_SMEM>>>(p_h, 4, c2_bl, 5, out);
}

// round 13
// speedup vs baseline: 1.0046x; 1.0046x over previous
#include <cuda_runtime.h>
#include <cuda_bf16.h>
#include <cstdint>

#define NN 100000
#define EE 1600000
#define DD 128

// Scratch (allocation-free rule: __device__ globals)
__device__ float g_h   [NN * DD];
__device__ float g_h2  [NN * DD];
__device__ float g_agg [NN * DD];
__device__ int   g_src [EE];
__device__ int   g_dst [EE];
__device__ int   g_esrc[EE];
__device__ int   g_degi[NN];
__device__ int   g_rowptr[NN + 1];
__device__ int   g_cursor[NN];
__device__ int   g_bsum[128];
__device__ int   g_boff[128];
__device__ int   g_is64;

// ===========================================================================
// PTX helpers (sm_80-compatible only: ldmatrix + mma.sync; NO tcgen05 — the
// harness compiles PTX at target compute_103, which rejects 'a' features)
// ===========================================================================
__device__ __forceinline__ uint32_t smem_u32(const void* p) {
    uint32_t a;
    asm("{ .reg .u64 t; cvta.to.shared.u64 t, %1; cvt.u32.u64 %0, t; }"
        : "=r"(a) : "l"(p));
    return a;
}
__device__ __forceinline__ void ldsm_x4(uint32_t* r, uint32_t addr) {
    asm volatile("ldmatrix.sync.aligned.m8n8.x4.shared.b16 {%0,%1,%2,%3}, [%4];"
                 : "=r"(r[0]), "=r"(r[1]), "=r"(r[2]), "=r"(r[3]) : "r"(addr));
}
__device__ __forceinline__ void mma16816(float* d, const uint32_t* a,
                                         const uint32_t* b) {
    asm volatile(
        "mma.sync.aligned.m16n8k16.row.col.f32.bf16.bf16.f32 "
        "{%0,%1,%2,%3}, {%4,%5,%6,%7}, {%8,%9}, {%0,%1,%2,%3};"
        : "+f"(d[0]), "+f"(d[1]), "+f"(d[2]), "+f"(d[3])
        : "r"(a[0]), "r"(a[1]), "r"(a[2]), "r"(a[3]), "r"(b[0]), "r"(b[1]));
}

// ===========================================================================
// Smem tile layout: bf16 [128][BSTRIDE], BSTRIDE=136.
// lin:  A_hi, A_lo, B_hi, B_lo           (4 regions, 139264 B)
// sage: A_hi, A_lo, BL_hi, BL_lo, BR_hi, BR_lo (6 regions, 208896 B)
// ===========================================================================
#define BSTRIDE 136
#define W_ELEMS (128 * BSTRIDE)       // 17408 bf16 per hi or lo region
#define TILE_B  (W_ELEMS * 2)         // 34816 bytes
#define R_A_HI  0
#define R_A_LO  (TILE_B)
#define R_B_HI  (2 * TILE_B)
#define LIN_SMEM  (4 * TILE_B)        // 139264
#define SAGE_SMEM (6 * TILE_B)        // 208896
#define GEMM_T   256                  // 8 warps, warp grid 4x2, tile 32x64

// Pre-converted weights: [6 weights][hi 17408 | lo 17408] bf16, smem layout.
__device__ __align__(16) __nv_bfloat16 g_wbf[6 * 2 * W_ELEMS];

// split fp32 pair -> bf16 hi/lo into A regions
__device__ __forceinline__ void cvt_store_pair(char* sm, int r, int c, float2 v) {
    __nv_bfloat16 h0 = __float2bfloat16(v.x);
    __nv_bfloat16 h1 = __float2bfloat16(v.y);
    __nv_bfloat16 l0 = __float2bfloat16(v.x - __bfloat162float(h0));
    __nv_bfloat16 l1 = __float2bfloat16(v.y - __bfloat162float(h1));
    uint32_t off = (uint32_t)(r * BSTRIDE + c) * 2;
    *reinterpret_cast<__nv_bfloat162*>(sm + R_A_HI + off) = __halves2bfloat162(h0, h1);
    *reinterpret_cast<__nv_bfloat162*>(sm + R_A_LO + off) = __halves2bfloat162(l0, l1);
}

// Weight prep: 16 blocks per weight, 256 threads, 4 elems/thread.
__global__ void prep_weights_kernel(const float* __restrict__ w0,
                                    const float* __restrict__ w1,
                                    const float* __restrict__ w2,
                                    const float* __restrict__ w3,
                                    const float* __restrict__ w4,
                                    const float* __restrict__ w5) {
    const float* ws[6] = {w0, w1, w2, w3, w4, w5};
    int w = blockIdx.x >> 4;
    int eb = ((blockIdx.x & 15) << 10) + (threadIdx.x << 2);   // elem base, mult of 4
    float4 v = *reinterpret_cast<const float4*>(ws[w] + eb);
    int r = eb >> 7, c = eb & 127;
    __nv_bfloat16 h0 = __float2bfloat16(v.x);
    __nv_bfloat16 h1 = __float2bfloat16(v.y);
    __nv_bfloat16 h2 = __float2bfloat16(v.z);
    __nv_bfloat16 h3 = __float2bfloat16(v.w);
    __nv_bfloat16 l0 = __float2bfloat16(v.x - __bfloat162float(h0));
    __nv_bfloat16 l1 = __float2bfloat16(v.y - __bfloat162float(h1));
    __nv_bfloat16 l2 = __float2bfloat16(v.z - __bfloat162float(h2));
    __nv_bfloat16 l3 = __float2bfloat16(v.w - __bfloat162float(h3));
    __nv_bfloat16* hi = g_wbf + (size_t)w * 2 * W_ELEMS;
    __nv_bfloat16* lo = hi + W_ELEMS;
    int o = r * BSTRIDE + c;
    *reinterpret_cast<__nv_bfloat162*>(hi + o)     = __halves2bfloat162(h0, h1);
    *reinterpret_cast<__nv_bfloat162*>(hi + o + 2) = __halves2bfloat162(h2, h3);
    *reinterpret_cast<__nv_bfloat162*>(lo + o)     = __halves2bfloat162(l0, l1);
    *reinterpret_cast<__nv_bfloat162*>(lo + o + 2) = __halves2bfloat162(l2, l3);
}

// Copy one pre-converted weight (hi+lo, contiguous 69632 B) into smem.
__device__ __forceinline__ void copy_weight(char* sm, uint32_t dstOff, int widx,
                                            int tid) {
    const uint4* src = reinterpret_cast<const uint4*>(g_wbf + (size_t)widx * 2 * W_ELEMS);
    uint4* dst = reinterpret_cast<uint4*>(sm + dstOff);
    #pragma unroll
    for (int i = 0; i < 17; i++) {
        int idx = tid + i * GEMM_T;
        dst[idx] = src[idx];
    }
}

// Mainloop: warp tile 32x64 (wr 0..3, wc 0..1), 3-term split, accumulate.
// bHi = smem offset of weight hi region; lo is contiguous at bHi + TILE_B.
__device__ __forceinline__ void mma_tile(uint32_t sb, float acc[2][8][4],
                                         int wr, int wc, int l, uint32_t bHi) {
    uint32_t bLo = bHi + TILE_B;
    #pragma unroll 2
    for (int k = 0; k < 8; k++) {
        uint32_t ah0[4], ah1[4], al0[4], al1[4];
        uint32_t arow0 = (uint32_t)(wr * 32 + (l & 15));
        uint32_t acolk = (uint32_t)(k * 16 + (l >> 4) * 8);
        uint32_t aoff0 = (arow0 * BSTRIDE + acolk) * 2;
        uint32_t aoff1 = ((arow0 + 16) * BSTRIDE + acolk) * 2;
        ldsm_x4(ah0, sb + R_A_HI + aoff0);
        ldsm_x4(ah1, sb + R_A_HI + aoff1);
        ldsm_x4(al0, sb + R_A_LO + aoff0);
        ldsm_x4(al1, sb + R_A_LO + aoff1);
        #pragma unroll
        for (int nfp = 0; nfp < 4; nfp++) {
            uint32_t bh4[4], bl4[4];
            uint32_t brow = (uint32_t)(wc * 64 + nfp * 16 + ((l >> 4) & 1) * 8 + (l & 7));
            uint32_t bcol = (uint32_t)(k * 16 + ((l >> 3) & 1) * 8);
            uint32_t boff = (brow * BSTRIDE + bcol) * 2;
            ldsm_x4(bh4, sb + bHi + boff);
            ldsm_x4(bl4, sb + bLo + boff);
            int nf0 = nfp * 2, nf1 = nfp * 2 + 1;
            mma16816(acc[0][nf0], ah0, bh4 + 0);
            mma16816(acc[1][nf0], ah1, bh4 + 0);
            mma16816(acc[0][nf1], ah0, bh4 + 2);
            mma16816(acc[1][nf1], ah1, bh4 + 2);
            mma16816(acc[0][nf0], ah0, bl4 + 0);
            mma16816(acc[1][nf0], ah1, bl4 + 0);
            mma16816(acc[0][nf1], ah0, bl4 + 2);
            mma16816(acc[1][nf1], ah1, bl4 + 2);
            mma16816(acc[0][nf0], al0, bh4 + 0);
            mma16816(acc[1][nf0], al1, bh4 + 0);
            mma16816(acc[0][nf1], al0, bh4 + 2);
            mma16816(acc[1][nf1], al1, bh4 + 2);
        }
    }
}

__device__ __forceinline__ void epilogue(float acc[2][8][4], const float* bias,
                                         float* Y, int rowBase, int wr, int wc,
                                         int l) {
    #pragma unroll
    for (int mf = 0; mf < 2; mf++) {
        #pragma unroll
        for (int nf = 0; nf < 8; nf++) {
            int col = wc * 64 + nf * 8 + (l & 3) * 2;
            float b0 = __ldg(bias + col), b1 = __ldg(bias + col + 1);
            int row0 = rowBase + wr * 32 + mf * 16 + (l >> 2);
            if (row0 < NN) {
                float2 v;
                v.x = fmaxf(acc[mf][nf][0] + b0, 0.f);
                v.y = fmaxf(acc[mf][nf][1] + b1, 0.f);
                *reinterpret_cast<float2*>(Y + (size_t)row0 * DD + col) = v;
            }
            int row1 = row0 + 8;
            if (row1 < NN) {
                float2 v;
                v.x = fmaxf(acc[mf][nf][2] + b0, 0.f);
                v.y = fmaxf(acc[mf][nf][3] + b1, 0.f);
                *reinterpret_cast<float2*>(Y + (size_t)row1 * DD + col) = v;
            }
        }
    }
}

// ===========================================================================
// Edge preprocessing: dtype detect, int32 edge lists, CSR build
// ===========================================================================
__global__ void detect_kernel(const long long* __restrict__ ei) {
    int t = threadIdx.x;
    long long v = ei[(size_t)(t & 15) * (EE / 16) + 3];
    unsigned bad = __ballot_sync(0xFFFFFFFF, v < 0 || v >= NN);
    if (t == 0) g_is64 = (bad == 0) ? 1 : 0;
}

__global__ void zero_degi_kernel() {
    int i = blockIdx.x * blockDim.x + threadIdx.x;
    if (i < NN) g_degi[i] = 0;
}

__global__ void convert_kernel(const void* __restrict__ ei_raw) {
    int e = blockIdx.x * blockDim.x + threadIdx.x;
    if (e >= EE) return;
    int s, d;
    if (g_is64) {
        const long long* ei = (const long long*)ei_raw;
        s = (int)ei[e];
        d = (int)ei[EE + e];
    } else {
        const int* ei = (const int*)ei_raw;
        s = ei[e];
        d = ei[EE + e];
    }
    g_src[e] = s;
    g_dst[e] = d;
    atomicAdd(&g_degi[d], 1);
}

// --- 3-phase parallel exclusive scan over g_degi -> g_rowptr / g_cursor ---
#define SCAN_BT 1024
#define SCAN_NB ((NN + SCAN_BT - 1) / SCAN_BT)   // 98

__global__ void scan_block_kernel() {
    __shared__ int ss[SCAN_BT];
    int t = threadIdx.x;
    int i = blockIdx.x * SCAN_BT + t;
    int v = (i < NN) ? g_degi[i] : 0;
    ss[t] = v;
    __syncthreads();
    for (int d = 1; d < SCAN_BT; d <<= 1) {
        int u = (t >= d) ? ss[t - d] : 0;
        __syncthreads();
        ss[t] += u;
        __syncthreads();
    }
    if (i < NN) g_rowptr[i] = ss[t] - v;   // exclusive within block
    if (t == SCAN_BT - 1) g_bsum[blockIdx.x] = ss[t];
}

__global__ void scan_bsum_kernel() {
    __shared__ int ss[128];
    int t = threadIdx.x;
    int v = (t < SCAN_NB) ? g_bsum[t] : 0;
    ss[t] = v;
    __syncthreads();
    for (int d = 1; d < 128; d <<= 1) {
        int u = (t >= d) ? ss[t - d] : 0;
        __syncthreads();
        ss[t] += u;
        __syncthreads();
    }
    g_boff[t] = ss[t] - v;   // exclusive
}

__global__ void scan_apply_kernel() {
    int i = blockIdx.x * SCAN_BT + threadIdx.x;
    if (i < NN) {
        int val = g_rowptr[i] + g_boff[blockIdx.x];
        g_rowptr[i] = val;
        g_cursor[i] = val;
    }
    if (i == 0) g_rowptr[NN] = EE;
}

__global__ void bucket_kernel() {
    int e = blockIdx.x * blockDim.x + threadIdx.x;
    if (e >= EE) return;
    int pos = atomicAdd(&g_cursor[g_dst[e]], 1);
    g_esrc[pos] = g_src[e];
}

// ===========================================================================
// Mean aggregation: warp per dst node, gather over CSR, write mean.
// ===========================================================================
__global__ void gather_mean_kernel(const float* __restrict__ H) {
    int w = (blockIdx.x * blockDim.x + threadIdx.x) >> 5;
    int lane = threadIdx.x & 31;
    if (w >= NN) return;
    int beg = g_rowptr[w], end = g_rowptr[w + 1];
    float4 acc = make_float4(0.f, 0.f, 0.f, 0.f);
    for (int base = beg; base < end; base += 32) {
        int cnt = min(32, end - base);
        int s = (lane < cnt) ? g_esrc[base + lane] : 0;
        for (int j = 0; j < cnt; j++) {
            int sj = __shfl_sync(0xFFFFFFFF, s, j);
            float4 v = reinterpret_cast<const float4*>(H + (size_t)sj * DD)[lane];
            acc.x += v.x; acc.y += v.y; acc.z += v.z; acc.w += v.w;
        }
    }
    float inv = (end > beg) ? 1.0f / (float)(end - beg) : 0.0f;
    acc.x *= inv; acc.y *= inv; acc.z *= inv; acc.w *= inv;
    reinterpret_cast<float4*>(g_agg + (size_t)w * DD)[lane] = acc;
}

// ===========================================================================
// GEMM 1: Y = relu(X @ W^T + b), weight pre-converted (index widx)
// ===========================================================================
__global__ __launch_bounds__(GEMM_T, 1)
void gemm_lin_kernel(const float* __restrict__ X, int widx,
                     const float* __restrict__ b, float* __restrict__ Y) {
    extern __shared__ char sm[];
    uint32_t sb = smem_u32(sm);
    int tid = threadIdx.x, wid = tid >> 5, l = tid & 31;
    int wr = wid >> 1, wc = wid & 1;
    int rowBase = blockIdx.x * 128;

    copy_weight(sm, R_B_HI, widx, tid);
    for (int idx = tid; idx < 128 * 64; idx += GEMM_T) {
        int r = idx >> 6, c = (idx & 63) * 2;
        int row = rowBase + r;
        float2 vx = make_float2(0.f, 0.f);
        if (row < NN) vx = *reinterpret_cast<const float2*>(X + (size_t)row * DD + c);
        cvt_store_pair(sm, r, c, vx);
    }
    __syncthreads();

    float acc[2][8][4];
    #pragma unroll
    for (int i = 0; i < 2; i++)
        #pragma unroll
        for (int j = 0; j < 8; j++)
            #pragma unroll
            for (int q = 0; q < 4; q++) acc[i][j][q] = 0.f;

    mma_tile(sb, acc, wr, wc, l, R_B_HI);
    epilogue(acc, b, Y, rowBase, wr, wc, l);
}

// ===========================================================================
// GEMM 2: Y = relu( mean @ Wl^T + bl + H @ Wr^T ), two phases, reg accum.
// Both weights resident in smem from the prologue.
// ===========================================================================
__global__ __launch_bounds__(GEMM_T, 1)
void gemm_sage_kernel(const float* __restrict__ H, int wl_idx,
                      const float* __restrict__ bl, int wr_idx,
                      float* __restrict__ Y) {
    extern __shared__ char sm[];
    uint32_t sb = smem_u32(sm);
    int tid = threadIdx.x, wid = tid >> 5, l = tid & 31;
    int wr = wid >> 1, wc = wid & 1;
    int rowBase = blockIdx.x * 128;

    copy_weight(sm, 2 * TILE_B, wl_idx, tid);
    copy_weight(sm, 4 * TILE_B, wr_idx, tid);
    // phase 1 A: mean
    for (int idx = tid; idx < 128 * 64; idx += GEMM_T) {
        int r = idx >> 6, c = (idx & 63) * 2;
        int row = rowBase + r;
        float2 va = make_float2(0.f, 0.f);
        if (row < NN) va = *reinterpret_cast<const float2*>(g_agg + (size_t)row * DD + c);
        cvt_store_pair(sm, r, c, va);
    }
    __syncthreads();

    float acc[2][8][4];
    #pragma unroll
    for (int i = 0; i < 2; i++)
        #pragma unroll
        for (int j = 0; j < 8; j++)
            #pragma unroll
            for (int q = 0; q < 4; q++) acc[i][j][q] = 0.f;

    mma_tile(sb, acc, wr, wc, l, 2 * TILE_B);
    __syncthreads();

    // phase 2 A: H
    for (int idx = tid; idx < 128 * 64; idx += GEMM_T) {
        int r = idx >> 6, c = (idx & 63) * 2;
        int row = rowBase + r;
        float2 va = make_float2(0.f, 0.f);
        if (row < NN) va = *reinterpret_cast<const float2*>(H + (size_t)row * DD + c);
        cvt_store_pair(sm, r, c, va);
    }
    __syncthreads();

    mma_tile(sb, acc, wr, wc, l, 4 * TILE_B);
    epilogue(acc, bl, Y, rowBase, wr, wc, l);
}

// ===========================================================================
extern "C" void kernel_launch(void* const* d_in, const int* in_sizes, int n_in,
                              void* d_out, int out_size) {
    const float* x     = (const float*)d_in[0];
    const void*  ei    = d_in[1];
    const float* W1    = (const float*)d_in[2];
    const float* b1    = (const float*)d_in[3];
    const float* W2    = (const float*)d_in[4];
    const float* b2    = (const float*)d_in[5];
    const float* c1_Wl = (const float*)d_in[6];
    const float* c1_bl = (const float*)d_in[7];
    const float* c1_Wr = (const float*)d_in[8];
    const float* c2_Wl = (const float*)d_in[9];
    const float* c2_bl = (const float*)d_in[10];
    const float* c2_Wr = (const float*)d_in[11];
    float* out = (float*)d_out;

    cudaFuncSetAttribute(gemm_lin_kernel,
                         cudaFuncAttributeMaxDynamicSharedMemorySize, LIN_SMEM);
    cudaFuncSetAttribute(gemm_sage_kernel,
                         cudaFuncAttributeMaxDynamicSharedMemorySize, SAGE_SMEM);

    float *p_h, *p_h2;
    cudaGetSymbolAddress((void**)&p_h, g_h);
    cudaGetSymbolAddress((void**)&p_h2, g_h2);

    int nb = (NN + 127) / 128;                      // 782 tiles
    int conv_blocks = (EE + 255) / 256;
    int gather_blocks = (NN * 32 + 255) / 256;      // one warp per node

    // Fork a non-blocking side stream for the CSR build so it overlaps the
    // layer-1 GEMM. Host-side stream/event creation happens only during the
    // correctness call and the single capture call (graph replays execute no
    // host code); no device memory is allocated.
    cudaStream_t sPre;
    cudaStreamCreateWithFlags(&sPre, cudaStreamNonBlocking);
    cudaEvent_t evFork, evJoin;
    cudaEventCreateWithFlags(&evFork, cudaEventDisableTiming);
    cudaEventCreateWithFlags(&evJoin, cudaEventDisableTiming);

    cudaEventRecord(evFork, 0);
    cudaStreamWaitEvent(sPre, evFork, 0);

    // --- side stream: edge preprocessing + CSR build ---
    detect_kernel<<<1, 32, 0, sPre>>>((const long long*)ei);
    zero_degi_kernel<<<(NN + 255) / 256, 256, 0, sPre>>>();
    convert_kernel<<<conv_blocks, 256, 0, sPre>>>(ei);
    scan_block_kernel<<<SCAN_NB, SCAN_BT, 0, sPre>>>();
    scan_bsum_kernel<<<1, 128, 0, sPre>>>();
    scan_apply_kernel<<<SCAN_NB, SCAN_BT, 0, sPre>>>();
    bucket_kernel<<<conv_blocks, 256, 0, sPre>>>();
    cudaEventRecord(evJoin, sPre);

    // --- main stream: weights + layer 1 (independent of CSR) ---
    prep_weights_kernel<<<96, 256>>>(W1, W2, c1_Wl, c1_Wr, c2_Wl, c2_Wr);
    gemm_lin_kernel<<<nb, GEMM_T, LIN_SMEM>>>(x, 0, b1, p_h);

    // join: gather needs both p_h and the CSR
    cudaStreamWaitEvent(0, evJoin, 0);

    // sage 1
    gather_mean_kernel<<<gather_blocks, 256>>>(p_h);
    gemm_sage_kernel<<<nb, GEMM_T, SAGE_SMEM>>>(p_h, 2, c1_bl, 3, p_h2);
    // layer 2
    gemm_lin_kernel<<<nb, GEMM_T, LIN_SMEM>>>(p_h2, 1, b2, p_h);
    // sage 2 -> out
    gather_mean_kernel<<<gather_blocks, 256>>>(p_h);
    gemm_sage_kernel<<<nb, GEMM_T, SAGE_SMEM>>>(p_h, 4, c2_bl, 5, out);
}